// round 16
// baseline (speedup 1.0000x reference)
#include <cuda_runtime.h>
#include <cuda_bf16.h>
#include <cuda_fp16.h>
#include <cstdint>

// Problem shape (fixed per reference): B=4, S=2048, D=1024, fp32.
#define BATCH 4
#define SEQ   2048
#define DIM   1024
#define MTOT  (BATCH * SEQ)          // 8192

// ---------------------------------------------------------------------------
// Scratch (device globals: allocation-guard safe).
// ---------------------------------------------------------------------------
__device__ __nv_bfloat16 g_xh[(size_t)MTOT * DIM], g_xl[(size_t)MTOT * DIM];
__device__ __half        g_x16[(size_t)MTOT * DIM];
__device__ __nv_bfloat16 g_wth[(size_t)2 * DIM * DIM], g_wtl[(size_t)2 * DIM * DIM];
__device__ __half        g_wv16[(size_t)DIM * DIM];        // [in(k), out(n)] natural
// q and k combined: [0 .. MTOT*DIM) = q, [MTOT*DIM ..) = k
__device__ __nv_bfloat16 g_qkh[(size_t)2 * MTOT * DIM], g_qkl[(size_t)2 * MTOT * DIM];
__device__ __half        g_v16[(size_t)MTOT * DIM];        // [s, d] natural
__device__ float         g_s [(size_t)BATCH * SEQ * SEQ];
__device__ __half        g_p16[(size_t)BATCH * SEQ * SEQ];

// ---------------------------------------------------------------------------
// PTX helpers (ldmatrix / mma / cp.async: all valid on plain sm_103 target)
// ---------------------------------------------------------------------------
__device__ __forceinline__ uint32_t smem_u32(const void* p) {
    return (uint32_t)__cvta_generic_to_shared(p);
}
__device__ __forceinline__ void ldsm_x4(uint32_t* r, uint32_t a) {
    asm volatile("ldmatrix.sync.aligned.m8n8.x4.shared.b16 {%0,%1,%2,%3},[%4];"
                 : "=r"(r[0]), "=r"(r[1]), "=r"(r[2]), "=r"(r[3]) : "r"(a));
}
__device__ __forceinline__ void ldsm_x4_t(uint32_t* r, uint32_t a) {
    asm volatile("ldmatrix.sync.aligned.m8n8.x4.trans.shared.b16 {%0,%1,%2,%3},[%4];"
                 : "=r"(r[0]), "=r"(r[1]), "=r"(r[2]), "=r"(r[3]) : "r"(a));
}
template<bool F16>
__device__ __forceinline__ void mma_any(float* c, const uint32_t* a,
                                        uint32_t b0, uint32_t b1) {
    if (F16)
        asm volatile(
            "mma.sync.aligned.m16n8k16.row.col.f32.f16.f16.f32 "
            "{%0,%1,%2,%3},{%4,%5,%6,%7},{%8,%9},{%0,%1,%2,%3};"
            : "+f"(c[0]), "+f"(c[1]), "+f"(c[2]), "+f"(c[3])
            : "r"(a[0]), "r"(a[1]), "r"(a[2]), "r"(a[3]), "r"(b0), "r"(b1));
    else
        asm volatile(
            "mma.sync.aligned.m16n8k16.row.col.f32.bf16.bf16.f32 "
            "{%0,%1,%2,%3},{%4,%5,%6,%7},{%8,%9},{%0,%1,%2,%3};"
            : "+f"(c[0]), "+f"(c[1]), "+f"(c[2]), "+f"(c[3])
            : "r"(a[0]), "r"(a[1]), "r"(a[2]), "r"(a[3]), "r"(b0), "r"(b1));
}
__device__ __forceinline__ void cpa16(uint32_t dst, const void* src) {
    asm volatile("cp.async.cg.shared.global [%0], [%1], 16;" :: "r"(dst), "l"(src));
}
__device__ __forceinline__ void cpa_commit() {
    asm volatile("cp.async.commit_group;" ::: "memory");
}
template<int N>
__device__ __forceinline__ void cpa_wait() {
    asm volatile("cp.async.wait_group %0;" :: "n"(N) : "memory");
}

// fp32 pair -> (hi, lo) bf16x2 packed words.  x = hi + lo + O(2^-17 |x|)
__device__ __forceinline__ void split_pack(float x, float y, uint32_t& hi, uint32_t& lo) {
    __nv_bfloat16 hx = __float2bfloat16(x);
    __nv_bfloat16 hy = __float2bfloat16(y);
    __nv_bfloat162 h2; h2.x = hx; h2.y = hy;
    __nv_bfloat162 l2;
    l2.x = __float2bfloat16(x - __bfloat162float(hx));
    l2.y = __float2bfloat16(y - __bfloat162float(hy));
    hi = *reinterpret_cast<uint32_t*>(&h2);
    lo = *reinterpret_cast<uint32_t*>(&l2);
}

// ---------------------------------------------------------------------------
// Generic split HMMA GEMM.  C[M,N] = A @ op(B) (+bias), fp32 accum.
//   PROD=3: A=(A0+A1), B=(B0+B1) K-major, 3 cross products (bf16 fp32-like).
//   PROD=1: single product (fp16 value path).
//   BT=false: B stored [N,K] row-major (op = B^T via K-major ldsm).
//   BT=true : B stored [K,N] row-major natural; ldmatrix.trans (PROD=1 only).
// CTA tile 128x128, 256 threads = 8 warps (4m x 2n), warp 32x64, K-chunk 32.
// Pipeline:
//   NST==2 : 2-stage, depth-2 produce, wait<1>, extra post-compute barrier
//            (PROD=3; 2 CTA/SM via 80KB smem).
//   NST>=3 : NST-stage ring, depth NST-1 produce-ahead, wait<NST-2>
//            (fp16 kernels; latency-bound -> deep prefetch).
// OUT=0: fp32 (+bias). OUT=1: split bf16 Ch/Cl (+bias). OUT=2: fp16 (+bias).
// blockIdx.z: batch / merged-GEMM selector via sA/sB/sC; bias0 (z==0)/bias1.
// ---------------------------------------------------------------------------
constexpr int LDROW = 80;                     // K-major row: 32 elems + 8 pad

// NOTE: __host__ __device__ — harness nvcc lacks --expt-relaxed-constexpr.
__host__ __device__ constexpr int stage_bytes(int prod, bool bt) {
    return (((prod == 3) ? 2 : 1) * 128) * LDROW
         + (bt ? 32 * (128 + 8) * 2 : ((prod == 3) ? 2 : 1) * 128 * LDROW);
}

template<int PROD, bool F16, int OUT, bool BIAS, int NST, bool BT>
__global__ __launch_bounds__(256, 2)
void g_gemm(const uint16_t* __restrict__ A0, const uint16_t* __restrict__ A1,
            const uint16_t* __restrict__ B0, const uint16_t* __restrict__ B1,
            const float* __restrict__ bias0, const float* __restrict__ bias1,
            float* __restrict__ C,
            __nv_bfloat16* __restrict__ Ch, __nv_bfloat16* __restrict__ Cl,
            int N, int K, size_t sA, size_t sB, size_t sC)
{
    constexpr int NA     = (PROD == 3) ? 2 : 1;
    constexpr int NB     = (PROD == 3) ? 2 : 1;
    constexpr int OFF_A0 = 0;
    constexpr int OFF_A1 = 128 * LDROW;
    constexpr int OFF_B0 = NA * 128 * LDROW;
    constexpr int OFF_B1 = OFF_B0 + 128 * LDROW;       // only when NB==2 (!BT)
    constexpr int LDBT   = 128 + 8;                    // BT row in elems
    constexpr int STAGE  = stage_bytes(PROD, BT);
    constexpr int DEPTH  = (NST == 2) ? 2 : NST - 1;   // produce-ahead distance
    constexpr int NPRO   = (NST == 2) ? 2 : NST - 1;   // prologue chunks
    constexpr int WAITN  = (NST == 2) ? 1 : NST - 2;   // wait_group bound

    extern __shared__ char sm[];
    const uint32_t sbase = smem_u32(sm);
    const int tid  = threadIdx.x;
    const int lane = tid & 31;
    const int warp = tid >> 5;
    const int brow = blockIdx.y * 128;
    const int bcol = blockIdx.x * 128;
    const size_t bz = blockIdx.z;
    const int mw = (warp & 3) * 32;
    const int nw = (warp >> 2) * 64;

    // ---- producer constants ----
    const int rr = tid >> 2;                      // 0..63 (K-major rows)
    const int c8 = tid & 3;                       // 16B chunk in 64B span
    const uint16_t* gA0 = A0 + bz * sA + (size_t)brow * K;
    const uint16_t* gA1 = (NA == 2) ? A1 + bz * sA + (size_t)brow * K : nullptr;
    const uint16_t* gB0 = BT ? B0 + bz * sB + bcol
                             : B0 + bz * sB + (size_t)bcol * K;
    const uint16_t* gB1 = (NB == 2) ? B1 + bz * sB + (size_t)bcol * K : nullptr;

    auto produce = [&](uint32_t sb, int k0) {
        #pragma unroll
        for (int j = 0; j < 2; j++) {             // 2 rows per thread
            const int r = rr + j * 64;
            const uint32_t so = (uint32_t)r * LDROW + c8 * 16;
            const size_t   go = (size_t)r * K + k0 + c8 * 8;
            cpa16(sb + OFF_A0 + so, gA0 + go);
            if (NA == 2) cpa16(sb + OFF_A1 + so, gA1 + go);
            if (!BT) {
                cpa16(sb + OFF_B0 + so, gB0 + go);
                if (NB == 2) cpa16(sb + OFF_B1 + so, gB1 + go);
            }
        }
        if (BT) {
            // 32 k-rows x 128 n-elems, natural [K,N] source rows
            const int krow = tid >> 3;            // 0..31
            const int cc   = tid & 7;
            #pragma unroll
            for (int j = 0; j < 2; j++) {
                const int c = cc + j * 8;         // 0..15
                cpa16(sb + OFF_B0 + (uint32_t)krow * LDBT * 2 + c * 16,
                      gB0 + (size_t)(k0 + krow) * N + c * 8);
            }
        }
    };

    float acc[2][8][4] = {};

    // ---- prologue ----
    #pragma unroll
    for (int p = 0; p < NPRO; p++) {
        produce(sbase + p * STAGE, p * 32);
        cpa_commit();
    }

    // ---- consumer lane constants ----
    const int r8      = lane & 7;
    const int aRowOff = r8 + ((lane >> 3) & 1) * 8;
    const int aColOff = ((lane >> 4) & 1) * 8;
    const int bRowOff = r8 + ((lane >> 4) & 1) * 8;   // NT: n-row
    const int bColOff = ((lane >> 3) & 1) * 8;        // NT: k-col
    const int btR     = r8 + ((lane >> 3) & 1) * 8;   // BT: k-row
    const int btC     = (lane >> 4) * 8;              // BT: n-col

    const int nt = K / 32;
    for (int t = 0; t < nt; t++) {
        cpa_wait<WAITN>();
        __syncthreads();
        const uint32_t sb = sbase + (t % NST) * STAGE;

        #pragma unroll
        for (int ks = 0; ks < 32; ks += 16) {
            uint32_t a0[2][4], a1[2][4];
            #pragma unroll
            for (int i = 0; i < 2; i++) {
                const uint32_t ao = (uint32_t)(mw + i * 16 + aRowOff) * LDROW
                                  + (ks + aColOff) * 2;
                ldsm_x4(a0[i], sb + OFF_A0 + ao);
                if (NA == 2) ldsm_x4(a1[i], sb + OFF_A1 + ao);
            }
            #pragma unroll
            for (int jp = 0; jp < 4; jp++) {
                uint32_t b0[4], b1[4];
                if (BT) {
                    const uint32_t bo = (uint32_t)(ks + btR) * LDBT
                                      + nw + jp * 16 + btC;
                    ldsm_x4_t(b0, sb + OFF_B0 + bo * 2);
                } else {
                    const uint32_t bo = (uint32_t)(nw + jp * 16 + bRowOff) * LDROW
                                      + (ks + bColOff) * 2;
                    ldsm_x4(b0, sb + OFF_B0 + bo);
                    if (NB == 2) ldsm_x4(b1, sb + OFF_B1 + bo);
                }
                #pragma unroll
                for (int i = 0; i < 2; i++) {
                    mma_any<F16>(acc[i][2 * jp],     a0[i], b0[0], b0[1]);
                    mma_any<F16>(acc[i][2 * jp + 1], a0[i], b0[2], b0[3]);
                    if (NB == 2) {
                        mma_any<F16>(acc[i][2 * jp],     a0[i], b1[0], b1[1]);
                        mma_any<F16>(acc[i][2 * jp + 1], a0[i], b1[2], b1[3]);
                    }
                    if (NA == 2) {
                        mma_any<F16>(acc[i][2 * jp],     a1[i], b0[0], b0[1]);
                        mma_any<F16>(acc[i][2 * jp + 1], a1[i], b0[2], b0[3]);
                    }
                }
            }
        }

        // WAR safety:
        //  NST==2: stage (t+2)%2 == t%2 is the one just computed -> need a
        //          post-compute barrier before overwriting it.
        //  NST>=3: stage (t+DEPTH)%NST == (t-1)%NST was last read at iter t-1,
        //          before the barrier at the top of THIS iter -> safe as-is.
        if (NST == 2) __syncthreads();
        if (t + DEPTH < nt)
            produce(sbase + ((t + DEPTH) % NST) * STAGE, (t + DEPTH) * 32);
        cpa_commit();   // always commit: uniform wait_group accounting
    }

    // ---- epilogue ----
    const float* bp = BIAS ? ((bz == 0) ? bias0 : bias1) : nullptr;
    const int g  = lane >> 2;
    const int tg = lane & 3;
    #pragma unroll
    for (int i = 0; i < 2; i++) {
        #pragma unroll
        for (int j = 0; j < 8; j++) {
            const int m = brow + mw + i * 16 + g;
            const int n = bcol + nw + j * 8 + tg * 2;
            float b0 = 0.f, b1 = 0.f;
            if (BIAS) { b0 = bp[n]; b1 = bp[n + 1]; }
            const float v00 = acc[i][j][0] + b0, v01 = acc[i][j][1] + b1;
            const float v10 = acc[i][j][2] + b0, v11 = acc[i][j][3] + b1;
            if (OUT == 0) {
                float* Cp = C + bz * sC;
                *(float2*)&Cp[(size_t)m * N + n]       = make_float2(v00, v01);
                *(float2*)&Cp[(size_t)(m + 8) * N + n] = make_float2(v10, v11);
            } else if (OUT == 1) {
                uint32_t h0, l0, h1, l1;
                split_pack(v00, v01, h0, l0);
                split_pack(v10, v11, h1, l1);
                __nv_bfloat16* Chp = Ch + bz * sC;
                __nv_bfloat16* Clp = Cl + bz * sC;
                *(uint32_t*)&Chp[(size_t)m * N + n]       = h0;
                *(uint32_t*)&Clp[(size_t)m * N + n]       = l0;
                *(uint32_t*)&Chp[(size_t)(m + 8) * N + n] = h1;
                *(uint32_t*)&Clp[(size_t)(m + 8) * N + n] = l1;
            } else {
                __half* Cp = (__half*)C + bz * sC;
                __half2 h0 = __floats2half2_rn(v00, v01);
                __half2 h1 = __floats2half2_rn(v10, v11);
                *(uint32_t*)&Cp[(size_t)m * N + n]       = *(uint32_t*)&h0;
                *(uint32_t*)&Cp[(size_t)(m + 8) * N + n] = *(uint32_t*)&h1;
            }
        }
    }
}

// ---------------------------------------------------------------------------
// convert_x: fp32 -> bf16 hi/lo split AND fp16 single, one pass over x.
// ---------------------------------------------------------------------------
__global__ __launch_bounds__(256)
void convert_x(const float4* __restrict__ X, uint32_t* __restrict__ Xh,
               uint32_t* __restrict__ Xl, uint32_t* __restrict__ X16)
{
    const size_t i = (size_t)blockIdx.x * 256 + threadIdx.x;
    float4 v = X[i];
    uint32_t h0, l0, h1, l1;
    split_pack(v.x, v.y, h0, l0);
    split_pack(v.z, v.w, h1, l1);
    Xh[2 * i] = h0; Xh[2 * i + 1] = h1;
    Xl[2 * i] = l0; Xl[2 * i + 1] = l1;
    __half2 p0 = __floats2half2_rn(v.x, v.y);
    __half2 p1 = __floats2half2_rn(v.z, v.w);
    X16[2 * i]     = *reinterpret_cast<uint32_t*>(&p0);
    X16[2 * i + 1] = *reinterpret_cast<uint32_t*>(&p1);
}

// ---------------------------------------------------------------------------
// convert_w3: one launch for all weights.
//   z=0: Wq -> transpose+split bf16 into Th/Tl[0];  z=1: Wk -> Th/Tl[+WOFF];
//   z=2: Wv -> straight fp32->fp16 (no transpose; BT GEMM consumes [in,out]).
// ---------------------------------------------------------------------------
__global__ __launch_bounds__(256)
void convert_w3(const float* __restrict__ Wq, const float* __restrict__ Wk,
                const float* __restrict__ Wv,
                __nv_bfloat16* __restrict__ Th, __nv_bfloat16* __restrict__ Tl,
                __half* __restrict__ T16)
{
    const int bx = blockIdx.x * 32, by = blockIdx.y * 32;
    const int x = threadIdx.x, y = threadIdx.y;
    const int z = blockIdx.z;
    if (z == 2) {
        #pragma unroll
        for (int r = 0; r < 4; r++) {
            const size_t o = (size_t)(by + y + 8 * r) * DIM + bx + x;
            T16[o] = __float2half(Wv[o]);
        }
        return;
    }
    __shared__ float t[32][33];
    const float* W = (z == 0) ? Wq : Wk;
    const size_t woff = (size_t)z * DIM * DIM;
    #pragma unroll
    for (int r = 0; r < 4; r++)
        t[y + 8 * r][x] = W[(size_t)(by + y + 8 * r) * DIM + bx + x];
    __syncthreads();
    #pragma unroll
    for (int r = 0; r < 4; r++) {
        float v = t[x][y + 8 * r];
        __nv_bfloat16 h = __float2bfloat16(v);
        __nv_bfloat16 l = __float2bfloat16(v - __bfloat162float(h));
        const size_t o = woff + (size_t)(bx + y + 8 * r) * DIM + by + x;
        Th[o] = h; Tl[o] = l;
    }
}

// ---------------------------------------------------------------------------
// Row softmax, length 2048, one warp per row; outputs single fp16 P.
// ---------------------------------------------------------------------------
__global__ __launch_bounds__(256)
void softmax_f16(const float* __restrict__ S, __half* __restrict__ P)
{
    const int lane = threadIdx.x & 31;
    const int w    = threadIdx.x >> 5;
    const size_t row = (size_t)blockIdx.x * 8 + w;
    const float4* p = reinterpret_cast<const float4*>(S + row * 2048);

    float4 v[16];
    #pragma unroll
    for (int i = 0; i < 16; i++) v[i] = p[lane + 32 * i];

    float m = -3.0e38f;
    #pragma unroll
    for (int i = 0; i < 16; i++)
        m = fmaxf(m, fmaxf(fmaxf(v[i].x, v[i].y), fmaxf(v[i].z, v[i].w)));
    #pragma unroll
    for (int o = 16; o; o >>= 1) m = fmaxf(m, __shfl_xor_sync(0xffffffffu, m, o));

    float s = 0.f;
    #pragma unroll
    for (int i = 0; i < 16; i++) {
        v[i].x = __expf(v[i].x - m); v[i].y = __expf(v[i].y - m);
        v[i].z = __expf(v[i].z - m); v[i].w = __expf(v[i].w - m);
        s += v[i].x + v[i].y + v[i].z + v[i].w;
    }
    #pragma unroll
    for (int o = 16; o; o >>= 1) s += __shfl_xor_sync(0xffffffffu, s, o);

    const float inv = 1.0f / s;
    uint32_t* op = reinterpret_cast<uint32_t*>(P) + row * 1024;
    #pragma unroll
    for (int i = 0; i < 16; i++) {
        __half2 p0 = __floats2half2_rn(v[i].x * inv, v[i].y * inv);
        __half2 p1 = __floats2half2_rn(v[i].z * inv, v[i].w * inv);
        const int c = lane + 32 * i;
        op[2 * c]     = *reinterpret_cast<uint32_t*>(&p0);
        op[2 * c + 1] = *reinterpret_cast<uint32_t*>(&p1);
    }
}

// ---------------------------------------------------------------------------
// Launch sequence.
// Inputs (metadata order): x, Wq, bq, Wk, bk, Wv, bv.  Output: [B,S,D] fp32.
// ---------------------------------------------------------------------------
extern "C" void kernel_launch(void* const* d_in, const int* in_sizes, int n_in,
                              void* d_out, int out_size)
{
    const float* x  = (const float*)d_in[0];
    const float* Wq = (const float*)d_in[1];
    const float* bq = (const float*)d_in[2];
    const float* Wk = (const float*)d_in[3];
    const float* bk = (const float*)d_in[4];
    const float* Wv = (const float*)d_in[5];
    const float* bv = (const float*)d_in[6];
    float* out = (float*)d_out;

    __nv_bfloat16 *xh, *xl, *wth, *wtl, *qkh, *qkl;
    __half *x16, *wv16, *v16, *p16;
    float *s;
    cudaGetSymbolAddress((void**)&xh,   g_xh);  cudaGetSymbolAddress((void**)&xl,  g_xl);
    cudaGetSymbolAddress((void**)&x16,  g_x16);
    cudaGetSymbolAddress((void**)&wth,  g_wth); cudaGetSymbolAddress((void**)&wtl, g_wtl);
    cudaGetSymbolAddress((void**)&wv16, g_wv16);
    cudaGetSymbolAddress((void**)&qkh,  g_qkh); cudaGetSymbolAddress((void**)&qkl, g_qkl);
    cudaGetSymbolAddress((void**)&v16,  g_v16);
    cudaGetSymbolAddress((void**)&s,    g_s);
    cudaGetSymbolAddress((void**)&p16,  g_p16);

    // smem: derived from the SAME stage_bytes() the kernel uses.
    const int SM_P3 = 2 * stage_bytes(3, false);   // 2 x 40960 =  81920 (2 CTA/SM)
    const int SM_BT = 5 * stage_bytes(1, true);    // 5 x 18944 =  94720 (2 CTA/SM)

    cudaFuncSetAttribute(g_gemm<3, false, 1, true,  2, false>,
                         cudaFuncAttributeMaxDynamicSharedMemorySize, SM_P3);
    cudaFuncSetAttribute(g_gemm<3, false, 0, false, 2, false>,
                         cudaFuncAttributeMaxDynamicSharedMemorySize, SM_P3);
    cudaFuncSetAttribute(g_gemm<1, true,  2, true,  5, true>,
                         cudaFuncAttributeMaxDynamicSharedMemorySize, SM_BT);
    cudaFuncSetAttribute(g_gemm<1, true,  0, false, 5, true>,
                         cudaFuncAttributeMaxDynamicSharedMemorySize, SM_BT);

    const size_t WOFF = (size_t)DIM * DIM;
    const size_t QKO  = (size_t)MTOT * DIM;          // k offset in g_qk*

    // 1) conversions (2 launches total)
    convert_x<<<(MTOT * DIM) / (256 * 4), 256>>>((const float4*)x,
        (uint32_t*)xh, (uint32_t*)xl, (uint32_t*)x16);
    convert_w3<<<dim3(DIM / 32, DIM / 32, 3), dim3(32, 8)>>>(
        Wq, Wk, Wv, wth, wtl, wv16);

    // 2) merged Q+K projection (bf16 3-product, 2-stage, 2 CTA/SM)
    const dim3 gqk(DIM / 128, MTOT / 128, 2);        // (8, 64, 2) = 1024 CTAs
    g_gemm<3, false, 1, true, 2, false><<<gqk, 256, SM_P3>>>(
        (const uint16_t*)xh, (const uint16_t*)xl,
        (const uint16_t*)wth, (const uint16_t*)wtl, bq, bk,
        nullptr, qkh, qkl, DIM, DIM, 0, WOFF, QKO);

    //    V projection: fp16 single product, 5-stage deep pipeline, BT weights.
    const dim3 gv(DIM / 128, MTOT / 128, 1);         // (8, 64) = 512 CTAs
    g_gemm<1, true, 2, true, 5, true><<<gv, 256, SM_BT>>>(
        (const uint16_t*)x16, nullptr,
        (const uint16_t*)wv16, nullptr, bv, bv,
        (float*)v16, nullptr, nullptr, DIM, DIM, 0, 0, 0);

    // 3) scores = Q @ K^T per batch -> fp32 S  (bf16 3-product)
    const dim3 gs(SEQ / 128, SEQ / 128, BATCH);      // (16, 16, 4) = 1024 CTAs
    g_gemm<3, false, 0, false, 2, false><<<gs, 256, SM_P3>>>(
        (const uint16_t*)qkh, (const uint16_t*)qkl,
        (const uint16_t*)(qkh + QKO), (const uint16_t*)(qkl + QKO),
        nullptr, nullptr,
        s, nullptr, nullptr, SEQ, DIM,
        (size_t)SEQ * DIM, (size_t)SEQ * DIM, (size_t)SEQ * SEQ);

    // 4) softmax -> P fp16
    softmax_f16<<<MTOT / 8, 256>>>(s, p16);

    // 5) out = P @ V per batch (fp16 single product, 5-stage deep pipeline)
    const dim3 go(DIM / 128, SEQ / 128, BATCH);      // (8, 16, 4) = 512 CTAs
    g_gemm<1, true, 0, false, 5, true><<<go, 256, SM_BT>>>(
        (const uint16_t*)p16, nullptr,
        (const uint16_t*)v16, nullptr, nullptr, nullptr,
        out, nullptr, nullptr, DIM, SEQ,
        (size_t)SEQ * SEQ, (size_t)SEQ * DIM, (size_t)SEQ * DIM);
}

// round 17
// speedup vs baseline: 1.0112x; 1.0112x over previous
#include <cuda_runtime.h>
#include <cuda_bf16.h>
#include <cuda_fp16.h>
#include <cstdint>

// Problem shape (fixed per reference): B=4, S=2048, D=1024, fp32.
#define BATCH 4
#define SEQ   2048
#define DIM   1024
#define MTOT  (BATCH * SEQ)          // 8192

// ---------------------------------------------------------------------------
// Scratch (device globals: allocation-guard safe).
// ---------------------------------------------------------------------------
__device__ __nv_bfloat16 g_xh[(size_t)MTOT * DIM], g_xl[(size_t)MTOT * DIM];
__device__ __half        g_x16[(size_t)MTOT * DIM];
__device__ __nv_bfloat16 g_wth[(size_t)2 * DIM * DIM], g_wtl[(size_t)2 * DIM * DIM];
__device__ __half        g_wv16[(size_t)DIM * DIM];        // [in(k), out(n)] natural
// q and k combined: [0 .. MTOT*DIM) = q, [MTOT*DIM ..) = k
__device__ __nv_bfloat16 g_qkh[(size_t)2 * MTOT * DIM], g_qkl[(size_t)2 * MTOT * DIM];
__device__ __half        g_v16[(size_t)MTOT * DIM];        // [s, d] natural
__device__ float         g_s [(size_t)BATCH * SEQ * SEQ];
__device__ __half        g_p16[(size_t)BATCH * SEQ * SEQ];

// ---------------------------------------------------------------------------
// PTX helpers (ldmatrix / mma / cp.async: all valid on plain sm_103 target)
// ---------------------------------------------------------------------------
__device__ __forceinline__ uint32_t smem_u32(const void* p) {
    return (uint32_t)__cvta_generic_to_shared(p);
}
__device__ __forceinline__ void ldsm_x4(uint32_t* r, uint32_t a) {
    asm volatile("ldmatrix.sync.aligned.m8n8.x4.shared.b16 {%0,%1,%2,%3},[%4];"
                 : "=r"(r[0]), "=r"(r[1]), "=r"(r[2]), "=r"(r[3]) : "r"(a));
}
__device__ __forceinline__ void ldsm_x4_t(uint32_t* r, uint32_t a) {
    asm volatile("ldmatrix.sync.aligned.m8n8.x4.trans.shared.b16 {%0,%1,%2,%3},[%4];"
                 : "=r"(r[0]), "=r"(r[1]), "=r"(r[2]), "=r"(r[3]) : "r"(a));
}
template<bool F16>
__device__ __forceinline__ void mma_any(float* c, const uint32_t* a,
                                        uint32_t b0, uint32_t b1) {
    if (F16)
        asm volatile(
            "mma.sync.aligned.m16n8k16.row.col.f32.f16.f16.f32 "
            "{%0,%1,%2,%3},{%4,%5,%6,%7},{%8,%9},{%0,%1,%2,%3};"
            : "+f"(c[0]), "+f"(c[1]), "+f"(c[2]), "+f"(c[3])
            : "r"(a[0]), "r"(a[1]), "r"(a[2]), "r"(a[3]), "r"(b0), "r"(b1));
    else
        asm volatile(
            "mma.sync.aligned.m16n8k16.row.col.f32.bf16.bf16.f32 "
            "{%0,%1,%2,%3},{%4,%5,%6,%7},{%8,%9},{%0,%1,%2,%3};"
            : "+f"(c[0]), "+f"(c[1]), "+f"(c[2]), "+f"(c[3])
            : "r"(a[0]), "r"(a[1]), "r"(a[2]), "r"(a[3]), "r"(b0), "r"(b1));
}
__device__ __forceinline__ void cpa16(uint32_t dst, const void* src) {
    asm volatile("cp.async.cg.shared.global [%0], [%1], 16;" :: "r"(dst), "l"(src));
}
__device__ __forceinline__ void cpa_commit() {
    asm volatile("cp.async.commit_group;" ::: "memory");
}
template<int N>
__device__ __forceinline__ void cpa_wait() {
    asm volatile("cp.async.wait_group %0;" :: "n"(N) : "memory");
}

// fp32 pair -> (hi, lo) bf16x2 packed words.  x = hi + lo + O(2^-17 |x|)
__device__ __forceinline__ void split_pack(float x, float y, uint32_t& hi, uint32_t& lo) {
    __nv_bfloat16 hx = __float2bfloat16(x);
    __nv_bfloat16 hy = __float2bfloat16(y);
    __nv_bfloat162 h2; h2.x = hx; h2.y = hy;
    __nv_bfloat162 l2;
    l2.x = __float2bfloat16(x - __bfloat162float(hx));
    l2.y = __float2bfloat16(y - __bfloat162float(hy));
    hi = *reinterpret_cast<uint32_t*>(&h2);
    lo = *reinterpret_cast<uint32_t*>(&l2);
}

// ---------------------------------------------------------------------------
// Generic split HMMA GEMM.  C[M,N] = A @ op(B) (+bias), fp32 accum.
//   PROD=3: A=(A0+A1), B=(B0+B1) K-major, 3 cross products (bf16 fp32-like).
//   PROD=1: single product (fp16 value path).
//   BT=false: B stored [N,K] row-major (op = B^T via K-major ldsm).
//   BT=true : B stored [K,N] row-major natural; ldmatrix.trans (PROD=1 only).
//   KCH: K-chunk per pipeline stage (32 for PROD=3; 64 for fp16 kernels --
//        doubles HMMA per barrier to amortize fixed per-chunk overhead).
// CTA tile 128x128, 256 threads = 8 warps (4m x 2n), warp 32x64.
// Pipeline: NST==2: depth-2 produce, wait<1>, extra post-compute barrier.
//           NST>=3: NST-stage ring, depth NST-1, wait<NST-2>.
// OUT=0: fp32 (+bias). OUT=1: split bf16 Ch/Cl (+bias). OUT=2: fp16 (+bias).
// blockIdx.z: batch / merged-GEMM selector via sA/sB/sC; bias0 (z==0)/bias1.
// ---------------------------------------------------------------------------

// NOTE: __host__ __device__ — harness nvcc lacks --expt-relaxed-constexpr.
__host__ __device__ constexpr int stage_bytes(int prod, bool bt, int kch) {
    return (((prod == 3) ? 2 : 1) * 128) * (kch + 8) * 2
         + (bt ? kch * (128 + 8) * 2
               : ((prod == 3) ? 2 : 1) * 128 * (kch + 8) * 2);
}

template<int PROD, bool F16, int OUT, bool BIAS, int NST, bool BT, int KCH>
__global__ __launch_bounds__(256, 2)
void g_gemm(const uint16_t* __restrict__ A0, const uint16_t* __restrict__ A1,
            const uint16_t* __restrict__ B0, const uint16_t* __restrict__ B1,
            const float* __restrict__ bias0, const float* __restrict__ bias1,
            float* __restrict__ C,
            __nv_bfloat16* __restrict__ Ch, __nv_bfloat16* __restrict__ Cl,
            int N, int K, size_t sA, size_t sB, size_t sC)
{
    constexpr int NA     = (PROD == 3) ? 2 : 1;
    constexpr int NB     = (PROD == 3) ? 2 : 1;
    constexpr int LDA_B  = (KCH + 8) * 2;              // K-major row bytes
    constexpr int OFF_A0 = 0;
    constexpr int OFF_A1 = 128 * LDA_B;
    constexpr int OFF_B0 = NA * 128 * LDA_B;
    constexpr int OFF_B1 = OFF_B0 + 128 * LDA_B;       // only when NB==2 (!BT)
    constexpr int LDBT   = 128 + 8;                    // BT row in elems
    constexpr int STAGE  = stage_bytes(PROD, BT, KCH);
    constexpr int DEPTH  = (NST == 2) ? 2 : NST - 1;   // produce-ahead distance
    constexpr int NPRO   = (NST == 2) ? 2 : NST - 1;   // prologue chunks
    constexpr int WAITN  = (NST == 2) ? 1 : NST - 2;   // wait_group bound
    constexpr int CPR    = KCH / 8;                    // 16B chunks per K-row
    constexpr int APT    = 128 * CPR / 256;            // chunks/thread/operand

    extern __shared__ char sm[];
    const uint32_t sbase = smem_u32(sm);
    const int tid  = threadIdx.x;
    const int lane = tid & 31;
    const int warp = tid >> 5;
    const int brow = blockIdx.y * 128;
    const int bcol = blockIdx.x * 128;
    const size_t bz = blockIdx.z;
    const int mw = (warp & 3) * 32;
    const int nw = (warp >> 2) * 64;

    // ---- producer constants ----
    const uint16_t* gA0 = A0 + bz * sA + (size_t)brow * K;
    const uint16_t* gA1 = (NA == 2) ? A1 + bz * sA + (size_t)brow * K : nullptr;
    const uint16_t* gB0 = BT ? B0 + bz * sB + bcol
                             : B0 + bz * sB + (size_t)bcol * K;
    const uint16_t* gB1 = (NB == 2) ? B1 + bz * sB + (size_t)bcol * K : nullptr;

    auto produce = [&](uint32_t sb, int k0) {
        #pragma unroll
        for (int p = 0; p < APT; p++) {               // K-major operands
            const int id = tid + p * 256;
            const int r = id / CPR, c = id % CPR;     // CPR power-of-2 -> shifts
            const uint32_t so = (uint32_t)r * LDA_B + c * 16;
            const size_t   go = (size_t)r * K + k0 + c * 8;
            cpa16(sb + OFF_A0 + so, gA0 + go);
            if (NA == 2) cpa16(sb + OFF_A1 + so, gA1 + go);
            if (!BT) {
                cpa16(sb + OFF_B0 + so, gB0 + go);
                if (NB == 2) cpa16(sb + OFF_B1 + so, gB1 + go);
            }
        }
        if (BT) {                                     // KCH k-rows x 128 n-elems
            #pragma unroll
            for (int p = 0; p < KCH / 16; p++) {
                const int id = tid + p * 256;
                const int kr = id >> 4, c = id & 15;
                cpa16(sb + OFF_B0 + (uint32_t)kr * (LDBT * 2) + c * 16,
                      gB0 + (size_t)(k0 + kr) * N + c * 8);
            }
        }
    };

    float acc[2][8][4] = {};

    // ---- prologue ----
    #pragma unroll
    for (int p = 0; p < NPRO; p++) {
        produce(sbase + p * STAGE, p * KCH);
        cpa_commit();
    }

    // ---- consumer lane constants ----
    const int r8      = lane & 7;
    const int aRowOff = r8 + ((lane >> 3) & 1) * 8;
    const int aColOff = ((lane >> 4) & 1) * 8;
    const int bRowOff = r8 + ((lane >> 4) & 1) * 8;   // NT: n-row
    const int bColOff = ((lane >> 3) & 1) * 8;        // NT: k-col
    const int btR     = r8 + ((lane >> 3) & 1) * 8;   // BT: k-row
    const int btC     = (lane >> 4) * 8;              // BT: n-col

    const int nt = K / KCH;
    for (int t = 0; t < nt; t++) {
        cpa_wait<WAITN>();
        __syncthreads();
        const uint32_t sb = sbase + (t % NST) * STAGE;

        #pragma unroll
        for (int ks = 0; ks < KCH; ks += 16) {
            uint32_t a0[2][4], a1[2][4];
            #pragma unroll
            for (int i = 0; i < 2; i++) {
                const uint32_t ao = (uint32_t)(mw + i * 16 + aRowOff) * LDA_B
                                  + (ks + aColOff) * 2;
                ldsm_x4(a0[i], sb + OFF_A0 + ao);
                if (NA == 2) ldsm_x4(a1[i], sb + OFF_A1 + ao);
            }
            #pragma unroll
            for (int jp = 0; jp < 4; jp++) {
                uint32_t b0[4], b1[4];
                if (BT) {
                    const uint32_t bo = (uint32_t)(ks + btR) * LDBT
                                      + nw + jp * 16 + btC;
                    ldsm_x4_t(b0, sb + OFF_B0 + bo * 2);
                } else {
                    const uint32_t bo = (uint32_t)(nw + jp * 16 + bRowOff) * LDA_B
                                      + (ks + bColOff) * 2;
                    ldsm_x4(b0, sb + OFF_B0 + bo);
                    if (NB == 2) ldsm_x4(b1, sb + OFF_B1 + bo);
                }
                #pragma unroll
                for (int i = 0; i < 2; i++) {
                    mma_any<F16>(acc[i][2 * jp],     a0[i], b0[0], b0[1]);
                    mma_any<F16>(acc[i][2 * jp + 1], a0[i], b0[2], b0[3]);
                    if (NB == 2) {
                        mma_any<F16>(acc[i][2 * jp],     a0[i], b1[0], b1[1]);
                        mma_any<F16>(acc[i][2 * jp + 1], a0[i], b1[2], b1[3]);
                    }
                    if (NA == 2) {
                        mma_any<F16>(acc[i][2 * jp],     a1[i], b0[0], b0[1]);
                        mma_any<F16>(acc[i][2 * jp + 1], a1[i], b0[2], b0[3]);
                    }
                }
            }
        }

        // WAR safety:
        //  NST==2: stage (t+2)%2 == t%2 is the one just computed -> need a
        //          post-compute barrier before overwriting it.
        //  NST>=3: stage (t+DEPTH)%NST == (t-1)%NST was last read at iter t-1,
        //          before the barrier at the top of THIS iter -> safe as-is.
        if (NST == 2) __syncthreads();
        if (t + DEPTH < nt)
            produce(sbase + ((t + DEPTH) % NST) * STAGE, (t + DEPTH) * KCH);
        cpa_commit();   // always commit: uniform wait_group accounting
    }

    // ---- epilogue ----
    const float* bp = BIAS ? ((bz == 0) ? bias0 : bias1) : nullptr;
    const int g  = lane >> 2;
    const int tg = lane & 3;
    #pragma unroll
    for (int i = 0; i < 2; i++) {
        #pragma unroll
        for (int j = 0; j < 8; j++) {
            const int m = brow + mw + i * 16 + g;
            const int n = bcol + nw + j * 8 + tg * 2;
            float b0 = 0.f, b1 = 0.f;
            if (BIAS) { b0 = bp[n]; b1 = bp[n + 1]; }
            const float v00 = acc[i][j][0] + b0, v01 = acc[i][j][1] + b1;
            const float v10 = acc[i][j][2] + b0, v11 = acc[i][j][3] + b1;
            if (OUT == 0) {
                float* Cp = C + bz * sC;
                *(float2*)&Cp[(size_t)m * N + n]       = make_float2(v00, v01);
                *(float2*)&Cp[(size_t)(m + 8) * N + n] = make_float2(v10, v11);
            } else if (OUT == 1) {
                uint32_t h0, l0, h1, l1;
                split_pack(v00, v01, h0, l0);
                split_pack(v10, v11, h1, l1);
                __nv_bfloat16* Chp = Ch + bz * sC;
                __nv_bfloat16* Clp = Cl + bz * sC;
                *(uint32_t*)&Chp[(size_t)m * N + n]       = h0;
                *(uint32_t*)&Clp[(size_t)m * N + n]       = l0;
                *(uint32_t*)&Chp[(size_t)(m + 8) * N + n] = h1;
                *(uint32_t*)&Clp[(size_t)(m + 8) * N + n] = l1;
            } else {
                __half* Cp = (__half*)C + bz * sC;
                __half2 h0 = __floats2half2_rn(v00, v01);
                __half2 h1 = __floats2half2_rn(v10, v11);
                *(uint32_t*)&Cp[(size_t)m * N + n]       = *(uint32_t*)&h0;
                *(uint32_t*)&Cp[(size_t)(m + 8) * N + n] = *(uint32_t*)&h1;
            }
        }
    }
}

// ---------------------------------------------------------------------------
// convert_x: fp32 -> bf16 hi/lo split AND fp16 single, one pass over x.
// ---------------------------------------------------------------------------
__global__ __launch_bounds__(256)
void convert_x(const float4* __restrict__ X, uint32_t* __restrict__ Xh,
               uint32_t* __restrict__ Xl, uint32_t* __restrict__ X16)
{
    const size_t i = (size_t)blockIdx.x * 256 + threadIdx.x;
    float4 v = X[i];
    uint32_t h0, l0, h1, l1;
    split_pack(v.x, v.y, h0, l0);
    split_pack(v.z, v.w, h1, l1);
    Xh[2 * i] = h0; Xh[2 * i + 1] = h1;
    Xl[2 * i] = l0; Xl[2 * i + 1] = l1;
    __half2 p0 = __floats2half2_rn(v.x, v.y);
    __half2 p1 = __floats2half2_rn(v.z, v.w);
    X16[2 * i]     = *reinterpret_cast<uint32_t*>(&p0);
    X16[2 * i + 1] = *reinterpret_cast<uint32_t*>(&p1);
}

// ---------------------------------------------------------------------------
// convert_w3: one launch for all weights.
//   z=0: Wq -> transpose+split bf16 into Th/Tl[0];  z=1: Wk -> Th/Tl[+WOFF];
//   z=2: Wv -> straight fp32->fp16 (no transpose; BT GEMM consumes [in,out]).
// ---------------------------------------------------------------------------
__global__ __launch_bounds__(256)
void convert_w3(const float* __restrict__ Wq, const float* __restrict__ Wk,
                const float* __restrict__ Wv,
                __nv_bfloat16* __restrict__ Th, __nv_bfloat16* __restrict__ Tl,
                __half* __restrict__ T16)
{
    const int bx = blockIdx.x * 32, by = blockIdx.y * 32;
    const int x = threadIdx.x, y = threadIdx.y;
    const int z = blockIdx.z;
    if (z == 2) {
        #pragma unroll
        for (int r = 0; r < 4; r++) {
            const size_t o = (size_t)(by + y + 8 * r) * DIM + bx + x;
            T16[o] = __float2half(Wv[o]);
        }
        return;
    }
    __shared__ float t[32][33];
    const float* W = (z == 0) ? Wq : Wk;
    const size_t woff = (size_t)z * DIM * DIM;
    #pragma unroll
    for (int r = 0; r < 4; r++)
        t[y + 8 * r][x] = W[(size_t)(by + y + 8 * r) * DIM + bx + x];
    __syncthreads();
    #pragma unroll
    for (int r = 0; r < 4; r++) {
        float v = t[x][y + 8 * r];
        __nv_bfloat16 h = __float2bfloat16(v);
        __nv_bfloat16 l = __float2bfloat16(v - __bfloat162float(h));
        const size_t o = woff + (size_t)(bx + y + 8 * r) * DIM + by + x;
        Th[o] = h; Tl[o] = l;
    }
}

// ---------------------------------------------------------------------------
// Row softmax, length 2048, one warp per row; outputs single fp16 P.
// ---------------------------------------------------------------------------
__global__ __launch_bounds__(256)
void softmax_f16(const float* __restrict__ S, __half* __restrict__ P)
{
    const int lane = threadIdx.x & 31;
    const int w    = threadIdx.x >> 5;
    const size_t row = (size_t)blockIdx.x * 8 + w;
    const float4* p = reinterpret_cast<const float4*>(S + row * 2048);

    float4 v[16];
    #pragma unroll
    for (int i = 0; i < 16; i++) v[i] = p[lane + 32 * i];

    float m = -3.0e38f;
    #pragma unroll
    for (int i = 0; i < 16; i++)
        m = fmaxf(m, fmaxf(fmaxf(v[i].x, v[i].y), fmaxf(v[i].z, v[i].w)));
    #pragma unroll
    for (int o = 16; o; o >>= 1) m = fmaxf(m, __shfl_xor_sync(0xffffffffu, m, o));

    float s = 0.f;
    #pragma unroll
    for (int i = 0; i < 16; i++) {
        v[i].x = __expf(v[i].x - m); v[i].y = __expf(v[i].y - m);
        v[i].z = __expf(v[i].z - m); v[i].w = __expf(v[i].w - m);
        s += v[i].x + v[i].y + v[i].z + v[i].w;
    }
    #pragma unroll
    for (int o = 16; o; o >>= 1) s += __shfl_xor_sync(0xffffffffu, s, o);

    const float inv = 1.0f / s;
    uint32_t* op = reinterpret_cast<uint32_t*>(P) + row * 1024;
    #pragma unroll
    for (int i = 0; i < 16; i++) {
        __half2 p0 = __floats2half2_rn(v[i].x * inv, v[i].y * inv);
        __half2 p1 = __floats2half2_rn(v[i].z * inv, v[i].w * inv);
        const int c = lane + 32 * i;
        op[2 * c]     = *reinterpret_cast<uint32_t*>(&p0);
        op[2 * c + 1] = *reinterpret_cast<uint32_t*>(&p1);
    }
}

// ---------------------------------------------------------------------------
// Launch sequence.
// Inputs (metadata order): x, Wq, bq, Wk, bk, Wv, bv.  Output: [B,S,D] fp32.
// ---------------------------------------------------------------------------
extern "C" void kernel_launch(void* const* d_in, const int* in_sizes, int n_in,
                              void* d_out, int out_size)
{
    const float* x  = (const float*)d_in[0];
    const float* Wq = (const float*)d_in[1];
    const float* bq = (const float*)d_in[2];
    const float* Wk = (const float*)d_in[3];
    const float* bk = (const float*)d_in[4];
    const float* Wv = (const float*)d_in[5];
    const float* bv = (const float*)d_in[6];
    float* out = (float*)d_out;

    __nv_bfloat16 *xh, *xl, *wth, *wtl, *qkh, *qkl;
    __half *x16, *wv16, *v16, *p16;
    float *s;
    cudaGetSymbolAddress((void**)&xh,   g_xh);  cudaGetSymbolAddress((void**)&xl,  g_xl);
    cudaGetSymbolAddress((void**)&x16,  g_x16);
    cudaGetSymbolAddress((void**)&wth,  g_wth); cudaGetSymbolAddress((void**)&wtl, g_wtl);
    cudaGetSymbolAddress((void**)&wv16, g_wv16);
    cudaGetSymbolAddress((void**)&qkh,  g_qkh); cudaGetSymbolAddress((void**)&qkl, g_qkl);
    cudaGetSymbolAddress((void**)&v16,  g_v16);
    cudaGetSymbolAddress((void**)&s,    g_s);
    cudaGetSymbolAddress((void**)&p16,  g_p16);

    // smem: derived from the SAME stage_bytes() the kernel uses.
    const int SM_P3 = 2 * stage_bytes(3, false, 32);   // 2 x 40960 =  81920
    const int SM_BT = 3 * stage_bytes(1, true,  64);   // 3 x 35840 = 107520

    cudaFuncSetAttribute(g_gemm<3, false, 1, true,  2, false, 32>,
                         cudaFuncAttributeMaxDynamicSharedMemorySize, SM_P3);
    cudaFuncSetAttribute(g_gemm<3, false, 0, false, 2, false, 32>,
                         cudaFuncAttributeMaxDynamicSharedMemorySize, SM_P3);
    cudaFuncSetAttribute(g_gemm<1, true,  2, true,  3, true,  64>,
                         cudaFuncAttributeMaxDynamicSharedMemorySize, SM_BT);
    cudaFuncSetAttribute(g_gemm<1, true,  0, false, 3, true,  64>,
                         cudaFuncAttributeMaxDynamicSharedMemorySize, SM_BT);

    const size_t WOFF = (size_t)DIM * DIM;
    const size_t QKO  = (size_t)MTOT * DIM;          // k offset in g_qk*

    // 1) conversions (2 launches total)
    convert_x<<<(MTOT * DIM) / (256 * 4), 256>>>((const float4*)x,
        (uint32_t*)xh, (uint32_t*)xl, (uint32_t*)x16);
    convert_w3<<<dim3(DIM / 32, DIM / 32, 3), dim3(32, 8)>>>(
        Wq, Wk, Wv, wth, wtl, wv16);

    // 2) merged Q+K projection (bf16 3-product, 2-stage, 2 CTA/SM)
    const dim3 gqk(DIM / 128, MTOT / 128, 2);        // (8, 64, 2) = 1024 CTAs
    g_gemm<3, false, 1, true, 2, false, 32><<<gqk, 256, SM_P3>>>(
        (const uint16_t*)xh, (const uint16_t*)xl,
        (const uint16_t*)wth, (const uint16_t*)wtl, bq, bk,
        nullptr, qkh, qkl, DIM, DIM, 0, WOFF, QKO);

    //    V projection: fp16 single product, K-chunk 64, BT weights.
    const dim3 gv(DIM / 128, MTOT / 128, 1);         // (8, 64) = 512 CTAs
    g_gemm<1, true, 2, true, 3, true, 64><<<gv, 256, SM_BT>>>(
        (const uint16_t*)x16, nullptr,
        (const uint16_t*)wv16, nullptr, bv, bv,
        (float*)v16, nullptr, nullptr, DIM, DIM, 0, 0, 0);

    // 3) scores = Q @ K^T per batch -> fp32 S  (bf16 3-product)
    const dim3 gs(SEQ / 128, SEQ / 128, BATCH);      // (16, 16, 4) = 1024 CTAs
    g_gemm<3, false, 0, false, 2, false, 32><<<gs, 256, SM_P3>>>(
        (const uint16_t*)qkh, (const uint16_t*)qkl,
        (const uint16_t*)(qkh + QKO), (const uint16_t*)(qkl + QKO),
        nullptr, nullptr,
        s, nullptr, nullptr, SEQ, DIM,
        (size_t)SEQ * DIM, (size_t)SEQ * DIM, (size_t)SEQ * SEQ);

    // 4) softmax -> P fp16
    softmax_f16<<<MTOT / 8, 256>>>(s, p16);

    // 5) out = P @ V per batch (fp16 single product, K-chunk 64)
    const dim3 go(DIM / 128, SEQ / 128, BATCH);      // (8, 16, 4) = 512 CTAs
    g_gemm<1, true, 0, false, 3, true, 64><<<go, 256, SM_BT>>>(
        (const uint16_t*)p16, nullptr,
        (const uint16_t*)v16, nullptr, nullptr, nullptr,
        out, nullptr, nullptr, DIM, SEQ,
        (size_t)SEQ * SEQ, (size_t)SEQ * DIM, (size_t)SEQ * DIM);
}